// round 13
// baseline (speedup 1.0000x reference)
#include <cuda_runtime.h>
#include <cstdint>

#define NB      16384
#define OWN_D   7
#define INTR_D  5
#define NH      3
#define HD      5
#define NI      256
#define HID     256
#define IN_DIM  (OWN_D + NH*HD)        // 22
#define OBS_D   (OWN_D + NI*INTR_D)    // 1287

// attention output x = [own, context]
__device__ float g_x[NB * IN_DIM];

typedef unsigned long long ull;

// ---------------------------------------------------------------------------
// helpers
// ---------------------------------------------------------------------------
__device__ __forceinline__ uint32_t s2u(const void* p) {
    uint32_t a;
    asm("{ .reg .u64 t; cvta.to.shared.u64 t, %1; cvt.u32.u64 %0, t; }"
        : "=r"(a) : "l"(p));
    return a;
}
__device__ __forceinline__ void fma2(ull& d, ull a, ull b) {
    asm("fma.rn.f32x2 %0, %1, %2, %0;" : "+l"(d) : "l"(a), "l"(b));
}
__device__ __forceinline__ void add2(ull& d, ull a) {
    asm("add.rn.f32x2 %0, %0, %1;" : "+l"(d) : "l"(a));
}
__device__ __forceinline__ ull pack2(float lo, float hi) {
    ull r; asm("mov.b64 %0, {%1, %2};" : "=l"(r) : "f"(lo), "f"(hi)); return r;
}
__device__ __forceinline__ void unpack2(ull v, float& lo, float& hi) {
    asm("mov.b64 {%0, %1}, %2;" : "=f"(lo), "=f"(hi) : "l"(v));
}
__device__ __forceinline__ float tanh_fast(float x) {
    float r;
    asm("tanh.approx.f32 %0, %1;" : "=f"(r) : "f"(x));
    return r;
}
__device__ __forceinline__ void cp_async16(uint32_t dst, const void* src) {
    asm volatile("cp.async.cg.shared.global [%0], [%1], 16;"
                 :: "r"(dst), "l"(src) : "memory");
}
__device__ __forceinline__ void cp_commit() {
    asm volatile("cp.async.commit_group;" ::: "memory");
}
__device__ __forceinline__ void cp_wait0() {
    asm volatile("cp.async.wait_group 0;" ::: "memory");
}

// ---------------------------------------------------------------------------
// Kernel A: additive attention, f32x2 item-pair version.
// 1 warp/row, 4 warps/CTA, 4 CTAs/SM.  Items in smem dim-major ->
// an item pair per dim is one LDS.64.  K-projection + softmax accumulation
// in packed f32x2 (per-item arithmetic identical to scalar version).
// ---------------------------------------------------------------------------
__global__ void __launch_bounds__(128, 4) attn_kernel(
    const float* __restrict__ obs,
    const float* __restrict__ Wq, const float* __restrict__ bq,
    const float* __restrict__ Wk, const float* __restrict__ bk,
    const float* __restrict__ Wv, const float* __restrict__ bv,
    const float* __restrict__ v_att, const float* __restrict__ temperature)
{
    __shared__ float sI[4][INTR_D][NI];            // 20 KB, dim-major per warp
    __shared__ float sWq[NH*HD*OWN_D];
    __shared__ float sWk[NH*HD*INTR_D];
    __shared__ float sWv[NH*HD*INTR_D];
    __shared__ float sbq[NH*HD], sbk[NH*HD], sbv[NH*HD], sva[NH*HD];

    const int tid = threadIdx.x;
    for (int i = tid; i < NH*HD*OWN_D;  i += 128) sWq[i] = Wq[i];
    for (int i = tid; i < NH*HD*INTR_D; i += 128) { sWk[i] = Wk[i]; sWv[i] = Wv[i]; }
    for (int i = tid; i < NH*HD;        i += 128) { sbq[i]=bq[i]; sbk[i]=bk[i]; sbv[i]=bv[i]; sva[i]=v_att[i]; }
    __syncthreads();

    const int warp = tid >> 5, lane = tid & 31;
    const int row  = blockIdx.x * 4 + warp;
    const float T  = fabsf(temperature[0]);
    const float* orow = obs + (size_t)row * OBS_D;

    // stage items dim-major (coalesced global reads)
    #pragma unroll
    for (int u = 0; u < 40; u++) {
        const int j = u*32 + lane;
        const int n = j / INTR_D;
        const int i = j - n*INTR_D;
        sI[warp][i][n] = __ldg(orow + OWN_D + j);
    }
    float own[OWN_D];
    #pragma unroll
    for (int o = 0; o < OWN_D; o++) own[o] = __ldg(orow + o);
    __syncwarp();

    // asum per pair half (pairs p = lane + 32g, items 2p, 2p+1)
    float asl[4], ash[4];
    #pragma unroll
    for (int g = 0; g < 4; g++) {
        const int p2 = 2*(lane + 32*g);
        float al = 0.0f, ah = 0.0f;
        #pragma unroll
        for (int i = 0; i < INTR_D; i++) {
            const ull x = *(const ull*)&sI[warp][i][p2];
            float lo, hi; unpack2(x, lo, hi);
            al += fabsf(lo); ah += fabsf(hi);
        }
        asl[g] = al; ash[g] = ah;
    }

    constexpr float L2E = 1.442695041f;

    #pragma unroll
    for (int h = 0; h < NH; h++) {
        // hoist head weights: packed-dup wk, qc; scalar vaT
        ull wkd[HD][INTR_D], qd[HD];
        float vaT[HD];
        float shift = 0.0f;
        #pragma unroll
        for (int d = 0; d < HD; d++) {
            const int hd = h*HD + d;
            float q = sbq[hd] + sbk[hd];
            #pragma unroll
            for (int o = 0; o < OWN_D; o++) q = fmaf(own[o], sWq[hd*OWN_D + o], q);
            qd[d]  = pack2(q, q);
            vaT[d] = T * sva[hd];
            shift += fabsf(vaT[d]);
            #pragma unroll
            for (int i = 0; i < INTR_D; i++) {
                const float w = sWk[hd*INTR_D + i];
                wkd[d][i] = pack2(w, w);
            }
        }
        const float sc0 = -shift;

        ull lp = 0ULL, sp[INTR_D];
        #pragma unroll
        for (int i = 0; i < INTR_D; i++) sp[i] = 0ULL;

        #pragma unroll
        for (int g = 0; g < 4; g++) {
            const int p2 = 2*(lane + 32*g);
            ull X[INTR_D];
            #pragma unroll
            for (int i = 0; i < INTR_D; i++)
                X[i] = *(const ull*)&sI[warp][i][p2];

            float sc_lo = sc0, sc_hi = sc0;
            #pragma unroll
            for (int d = 0; d < HD; d++) {
                ull k = qd[d];
                #pragma unroll
                for (int i = 0; i < INTR_D; i++) fma2(k, X[i], wkd[d][i]);
                float klo, khi; unpack2(k, klo, khi);
                sc_lo = fmaf(vaT[d], tanh_fast(klo), sc_lo);
                sc_hi = fmaf(vaT[d], tanh_fast(khi), sc_hi);
            }
            float pwlo = exp2f(sc_lo * L2E);
            float pwhi = exp2f(sc_hi * L2E);
            if (asl[g] < 1e-6f) pwlo = 0.0f;
            if (ash[g] < 1e-6f) pwhi = 0.0f;
            const ull pw = pack2(pwlo, pwhi);

            add2(lp, pw);
            #pragma unroll
            for (int i = 0; i < INTR_D; i++) fma2(sp[i], pw, X[i]);
        }

        // fold pair halves to scalars
        float l, s[INTR_D];
        {
            float lo, hi; unpack2(lp, lo, hi); l = lo + hi;
            #pragma unroll
            for (int i = 0; i < INTR_D; i++) {
                unpack2(sp[i], lo, hi); s[i] = lo + hi;
            }
        }

        #pragma unroll
        for (int off = 16; off > 0; off >>= 1) {
            l += __shfl_xor_sync(0xffffffffu, l, off);
            #pragma unroll
            for (int i = 0; i < INTR_D; i++)
                s[i] += __shfl_xor_sync(0xffffffffu, s[i], off);
        }

        if (lane == 0) {
            const float gate = (l > 0.0f) ? 1.0f : 0.0f;
            const float inv  = (l > 0.0f) ? __fdividef(1.0f, l) : 0.0f;
            const float t0 = s[0]*inv, t1 = s[1]*inv, t2 = s[2]*inv,
                        t3 = s[3]*inv, t4 = s[4]*inv;
            #pragma unroll
            for (int d = 0; d < HD; d++) {
                const int hd = h*HD + d;
                float c = sbv[hd];
                c = fmaf(t0, sWv[hd*INTR_D + 0], c);
                c = fmaf(t1, sWv[hd*INTR_D + 1], c);
                c = fmaf(t2, sWv[hd*INTR_D + 2], c);
                c = fmaf(t3, sWv[hd*INTR_D + 3], c);
                c = fmaf(t4, sWv[hd*INTR_D + 4], c);
                g_x[(size_t)row*IN_DIM + OWN_D + hd] = c * gate;
            }
        }
    }

    if (lane < OWN_D) g_x[(size_t)row*IN_DIM + lane] = __ldg(orow + lane);
}

// ---------------------------------------------------------------------------
// Kernel B: fused MLP (FFMA2) — R10 verbatim (proven 65.8us).
// CTA = 32 rows x 256 cols, 128 threads (4 warps), grid 512, 4 CTAs/SM.
// Lane cols [ct*4..+3] and [128+ct*4..+3]; warp = 8 rows (8x8 microtile).
// k-chunk 16; W2 + x1 double-buffered; x1 computed inline per chunk.
// ---------------------------------------------------------------------------
#define KCH    16
#define NCHUNK (HID/KCH)                     // 16
#define X1STR  68                            // floats: 64 dup + 4 pad
#define OFF_W2 0                             // [2][KCH][256] f32 = 32768 B
#define OFF_X1 32768                         // [2][KCH][X1STR] f32 = 8704 B
#define OFF_SX (32768 + 8704)                // [32][22] f32 = 2816 B
#define SMEM_MLP (OFF_SX + 2816)             // 44288 B

__global__ void __launch_bounds__(128, 4) mlp_kernel(
    const float* __restrict__ W1, const float* __restrict__ b1,
    const float* __restrict__ W2, const float* __restrict__ b2,
    const float* __restrict__ Wf, const float* __restrict__ bf,
    const float* __restrict__ log_std, float* __restrict__ out)
{
    extern __shared__ __align__(16) char dsm[];
    float* sW2 = (float*)(dsm + OFF_W2);
    float* sX1 = (float*)(dsm + OFF_X1);
    float* sX  = (float*)(dsm + OFF_SX);
    const uint32_t w2b = s2u(sW2);

    const int tid  = threadIdx.x;
    const int ct   = tid & 31;               // lane
    const int rg   = tid >> 5;               // warp: rows r0..r0+7
    const int cl   = ct * 4;                 // low-half col base
    const int r0   = rg * 8;
    const int row0 = blockIdx.x * 32;

    // x1-compute mapping: col = kk + (tid&15), rows 4q..4q+3
    const int xc = tid & 15;
    const int q  = tid >> 4;

    // prefetch W2 chunk 0 (16KB, 128 threads x 8 x 16B)
    #pragma unroll
    for (int u = 0; u < 8; u++) {
        const int idx = u*128 + tid;
        cp_async16(w2b + idx*16, W2 + idx*4);
    }
    cp_commit();

    // stage x rows
    for (int i = tid; i < 32*IN_DIM; i += 128)
        sX[i] = g_x[(size_t)row0*IN_DIM + i];
    __syncthreads();

    ull acc[8][4];                 // [row j][p]: p<2 -> cl+2p, p>=2 -> 128+cl+2(p-2)
    #pragma unroll
    for (int j = 0; j < 8; j++)
        #pragma unroll
        for (int p = 0; p < 4; p++) acc[j][p] = 0ULL;

    for (int ch = 0; ch < NCHUNK; ch++) {
        const int kk  = ch * KCH;
        const int buf = ch & 1;

        // ---- x1 for col kk+xc, rows 4q..4q+3 (write duplicated pairs) ----
        {
            const float bb = __ldg(b1 + kk + xc);
            float a0 = bb, a1 = bb, a2 = bb, a3 = bb;
            const float* w1c = W1 + kk + xc;
            const float* xr = sX + (4*q)*IN_DIM;
            #pragma unroll
            for (int i = 0; i < IN_DIM; i++) {
                const float wv = __ldg(w1c + i*HID);
                a0 = fmaf(xr[i],            wv, a0);
                a1 = fmaf(xr[IN_DIM+i],     wv, a1);
                a2 = fmaf(xr[2*IN_DIM+i],   wv, a2);
                a3 = fmaf(xr[3*IN_DIM+i],   wv, a3);
            }
            a0 = (a0 > 0.0f) ? a0 : 0.2f*a0;
            a1 = (a1 > 0.0f) ? a1 : 0.2f*a1;
            a2 = (a2 > 0.0f) ? a2 : 0.2f*a2;
            a3 = (a3 > 0.0f) ? a3 : 0.2f*a3;
            float* xd = sX1 + buf*(KCH*X1STR) + xc*X1STR + 8*q;
            *(float4*)(xd)     = make_float4(a0, a0, a1, a1);
            *(float4*)(xd + 4) = make_float4(a2, a2, a3, a3);
        }

        cp_wait0();            // W2 chunk ch landed
        __syncthreads();       // x1[buf] + W2[buf] visible (4-warp barrier)

        // prefetch next W2 chunk (overlaps FFMA2 loop)
        if (ch < NCHUNK-1) {
            const uint32_t dst = w2b + (buf ^ 1)*(KCH*256*4);
            const float* src = W2 + (size_t)(kk + KCH)*HID;
            #pragma unroll
            for (int u = 0; u < 8; u++) {
                const int idx = u*128 + tid;
                cp_async16(dst + idx*16, src + idx*4);
            }
            cp_commit();
        }

        // ---- FFMA2 inner loop: W loads lane-contiguous (4 wavefronts) ----
        const float* Wb = sW2 + buf*(KCH*256);
        const float* Xb = sX1 + buf*(KCH*X1STR) + 2*r0;
        #pragma unroll
        for (int k = 0; k < KCH; k++) {
            const ulonglong2* xp = (const ulonglong2*)(Xb + k*X1STR);
            const ulonglong2 xa = xp[0], xb_ = xp[1], xc_ = xp[2], xd_ = xp[3];
            const ulonglong2 wa = *(const ulonglong2*)(Wb + k*256 + cl);
            const ulonglong2 wb_ = *(const ulonglong2*)(Wb + k*256 + 128 + cl);

            fma2(acc[0][0], xa.x,  wa.x);  fma2(acc[0][1], xa.x,  wa.y);
            fma2(acc[0][2], xa.x,  wb_.x); fma2(acc[0][3], xa.x,  wb_.y);
            fma2(acc[1][0], xa.y,  wa.x);  fma2(acc[1][1], xa.y,  wa.y);
            fma2(acc[1][2], xa.y,  wb_.x); fma2(acc[1][3], xa.y,  wb_.y);
            fma2(acc[2][0], xb_.x, wa.x);  fma2(acc[2][1], xb_.x, wa.y);
            fma2(acc[2][2], xb_.x, wb_.x); fma2(acc[2][3], xb_.x, wb_.y);
            fma2(acc[3][0], xb_.y, wa.x);  fma2(acc[3][1], xb_.y, wa.y);
            fma2(acc[3][2], xb_.y, wb_.x); fma2(acc[3][3], xb_.y, wb_.y);
            fma2(acc[4][0], xc_.x, wa.x);  fma2(acc[4][1], xc_.x, wa.y);
            fma2(acc[4][2], xc_.x, wb_.x); fma2(acc[4][3], xc_.x, wb_.y);
            fma2(acc[5][0], xc_.y, wa.x);  fma2(acc[5][1], xc_.y, wa.y);
            fma2(acc[5][2], xc_.y, wb_.x); fma2(acc[5][3], xc_.y, wb_.y);
            fma2(acc[6][0], xd_.x, wa.x);  fma2(acc[6][1], xd_.x, wa.y);
            fma2(acc[6][2], xd_.x, wb_.x); fma2(acc[6][3], xd_.x, wb_.y);
            fma2(acc[7][0], xd_.y, wa.x);  fma2(acc[7][1], xd_.y, wa.y);
            fma2(acc[7][2], xd_.y, wb_.x); fma2(acc[7][3], xd_.y, wb_.y);
        }
    }

    // ---- epilogue: b2 + leaky + Wf projection ----
    float po0[8], po1[8];
    #pragma unroll
    for (int j = 0; j < 8; j++) { po0[j] = 0.0f; po1[j] = 0.0f; }

    #pragma unroll
    for (int p = 0; p < 4; p++) {
        const int c = (p < 2) ? (cl + 2*p) : (128 + cl + 2*(p - 2));
        const float b2a = __ldg(b2 + c),       b2b = __ldg(b2 + c + 1);
        const float wa0 = __ldg(Wf + c*2),     wa1 = __ldg(Wf + c*2 + 1);
        const float wb0 = __ldg(Wf + c*2 + 2), wb1 = __ldg(Wf + c*2 + 3);
        #pragma unroll
        for (int j = 0; j < 8; j++) {
            float vl, vh;
            unpack2(acc[j][p], vl, vh);
            vl += b2a; vl = (vl > 0.0f) ? vl : 0.2f*vl;
            vh += b2b; vh = (vh > 0.0f) ? vh : 0.2f*vh;
            po0[j] += vl*wa0 + vh*wb0;
            po1[j] += vl*wa1 + vh*wb1;
        }
    }

    #pragma unroll
    for (int off = 16; off > 0; off >>= 1) {
        #pragma unroll
        for (int j = 0; j < 8; j++) {
            po0[j] += __shfl_xor_sync(0xffffffffu, po0[j], off);
            po1[j] += __shfl_xor_sync(0xffffffffu, po1[j], off);
        }
    }

    if (ct == 0) {
        const float bf0 = __ldg(bf + 0), bf1 = __ldg(bf + 1);
        const float ls0 = __ldg(log_std + 0), ls1 = __ldg(log_std + 1);
        #pragma unroll
        for (int j = 0; j < 8; j++) {
            float4 o;
            o.x = po0[j] + bf0;
            o.y = po1[j] + bf1;
            o.z = ls0;
            o.w = ls1;
            *(float4*)&out[(size_t)(row0 + r0 + j)*4] = o;
        }
    }
}

// ---------------------------------------------------------------------------
extern "C" void kernel_launch(void* const* d_in, const int* in_sizes, int n_in,
                              void* d_out, int out_size)
{
    const float* obs         = (const float*)d_in[0];
    const float* Wq          = (const float*)d_in[1];
    const float* bq          = (const float*)d_in[2];
    const float* Wk          = (const float*)d_in[3];
    const float* bk          = (const float*)d_in[4];
    const float* Wv          = (const float*)d_in[5];
    const float* bv          = (const float*)d_in[6];
    const float* v_att       = (const float*)d_in[7];
    const float* temperature = (const float*)d_in[8];
    const float* W1          = (const float*)d_in[9];
    const float* b1          = (const float*)d_in[10];
    const float* W2          = (const float*)d_in[11];
    const float* b2          = (const float*)d_in[12];
    const float* Wf          = (const float*)d_in[13];
    const float* bf          = (const float*)d_in[14];
    const float* log_std     = (const float*)d_in[15];
    float* out = (float*)d_out;

    cudaFuncSetAttribute(mlp_kernel,
                         cudaFuncAttributeMaxDynamicSharedMemorySize,
                         SMEM_MLP);

    attn_kernel<<<NB/4, 128>>>(obs, Wq, bq, Wk, bk, Wv, bv, v_att, temperature);
    mlp_kernel<<<NB/32, 128, SMEM_MLP>>>(W1, b1, W2, b2, Wf, bf, log_std, out);
}

// round 14
// speedup vs baseline: 1.9984x; 1.9984x over previous
#include <cuda_runtime.h>
#include <cstdint>

#define NB      16384
#define OWN_D   7
#define INTR_D  5
#define NH      3
#define HD      5
#define NI      256
#define HID     256
#define IN_DIM  (OWN_D + NH*HD)        // 22
#define OBS_D   (OWN_D + NI*INTR_D)    // 1287

// attention output x = [own, context]
__device__ float g_x[NB * IN_DIM];

typedef unsigned long long ull;

// ---------------------------------------------------------------------------
// helpers
// ---------------------------------------------------------------------------
__device__ __forceinline__ uint32_t s2u(const void* p) {
    uint32_t a;
    asm("{ .reg .u64 t; cvta.to.shared.u64 t, %1; cvt.u32.u64 %0, t; }"
        : "=r"(a) : "l"(p));
    return a;
}
__device__ __forceinline__ void fma2(ull& d, ull a, ull b) {
    asm("fma.rn.f32x2 %0, %1, %2, %0;" : "+l"(d) : "l"(a), "l"(b));
}
__device__ __forceinline__ ull pack2(float lo, float hi) {
    ull r; asm("mov.b64 %0, {%1, %2};" : "=l"(r) : "f"(lo), "f"(hi)); return r;
}
__device__ __forceinline__ void unpack2(ull v, float& lo, float& hi) {
    asm("mov.b64 {%0, %1}, %2;" : "=f"(lo), "=f"(hi) : "l"(v));
}
__device__ __forceinline__ float tanh_fast(float x) {
    float r;
    asm("tanh.approx.f32 %0, %1;" : "=f"(r) : "f"(x));
    return r;
}
__device__ __forceinline__ void cp_async16(uint32_t dst, const void* src) {
    asm volatile("cp.async.cg.shared.global [%0], [%1], 16;"
                 :: "r"(dst), "l"(src) : "memory");
}
__device__ __forceinline__ void cp_commit() {
    asm volatile("cp.async.commit_group;" ::: "memory");
}
__device__ __forceinline__ void cp_wait0() {
    asm volatile("cp.async.wait_group 0;" ::: "memory");
}

// ---------------------------------------------------------------------------
// Kernel A: additive attention — R10 scalar version (proven ~33us)
// ---------------------------------------------------------------------------
__global__ void __launch_bounds__(128, 4) attn_kernel(
    const float* __restrict__ obs,
    const float* __restrict__ Wq, const float* __restrict__ bq,
    const float* __restrict__ Wk, const float* __restrict__ bk,
    const float* __restrict__ Wv, const float* __restrict__ bv,
    const float* __restrict__ v_att, const float* __restrict__ temperature)
{
    __shared__ float sWq[NH*HD*OWN_D];
    __shared__ float sWk[NH*HD*INTR_D];
    __shared__ float sWv[NH*HD*INTR_D];
    __shared__ float sbq[NH*HD], sbk[NH*HD], sbv[NH*HD], sva[NH*HD];

    const int tid = threadIdx.x;
    for (int i = tid; i < NH*HD*OWN_D;  i += 128) sWq[i] = Wq[i];
    for (int i = tid; i < NH*HD*INTR_D; i += 128) { sWk[i] = Wk[i]; sWv[i] = Wv[i]; }
    for (int i = tid; i < NH*HD;        i += 128) { sbq[i]=bq[i]; sbk[i]=bk[i]; sbv[i]=bv[i]; sva[i]=v_att[i]; }
    __syncthreads();

    const int warp = tid >> 5, lane = tid & 31;
    const int row  = blockIdx.x * 4 + warp;
    const float T  = fabsf(temperature[0]);
    const float* orow = obs + (size_t)row * OBS_D;

    float own[OWN_D];
    #pragma unroll
    for (int o = 0; o < OWN_D; o++) own[o] = __ldg(orow + o);

    float it[8][INTR_D];
    #pragma unroll
    for (int t = 0; t < 8; t++) {
        const float* p = orow + OWN_D + ((t << 5) + lane) * INTR_D;
        #pragma unroll
        for (int i = 0; i < INTR_D; i++) it[t][i] = __ldg(p + i);
    }
    float asum[8];
    #pragma unroll
    for (int t = 0; t < 8; t++)
        asum[t] = fabsf(it[t][0])+fabsf(it[t][1])+fabsf(it[t][2])
                 +fabsf(it[t][3])+fabsf(it[t][4]);

    constexpr float L2E = 1.442695041f;

    #pragma unroll
    for (int h = 0; h < NH; h++) {
        float wk[HD][INTR_D], qc[HD], vaT[HD];
        float shift = 0.0f;
        #pragma unroll
        for (int d = 0; d < HD; d++) {
            const int hd = h*HD + d;
            float q = sbq[hd] + sbk[hd];
            #pragma unroll
            for (int o = 0; o < OWN_D; o++) q = fmaf(own[o], sWq[hd*OWN_D + o], q);
            qc[d]  = q;
            vaT[d] = T * sva[hd];
            shift += fabsf(vaT[d]);
            #pragma unroll
            for (int i = 0; i < INTR_D; i++) wk[d][i] = sWk[hd*INTR_D + i];
        }

        float l = 0.0f, s0 = 0.f, s1 = 0.f, s2 = 0.f, s3 = 0.f, s4 = 0.f;

        #pragma unroll
        for (int t = 0; t < 8; t++) {
            const float x0 = it[t][0], x1 = it[t][1], x2 = it[t][2],
                        x3 = it[t][3], x4 = it[t][4];
            float sc = -shift;
            #pragma unroll
            for (int d = 0; d < HD; d++) {
                float k = qc[d];
                k = fmaf(x0, wk[d][0], k);
                k = fmaf(x1, wk[d][1], k);
                k = fmaf(x2, wk[d][2], k);
                k = fmaf(x3, wk[d][3], k);
                k = fmaf(x4, wk[d][4], k);
                sc = fmaf(vaT[d], tanh_fast(k), sc);
            }
            float pw = exp2f(sc * L2E);
            if (asum[t] < 1e-6f) pw = 0.0f;

            l += pw;
            s0 = fmaf(pw, x0, s0);
            s1 = fmaf(pw, x1, s1);
            s2 = fmaf(pw, x2, s2);
            s3 = fmaf(pw, x3, s3);
            s4 = fmaf(pw, x4, s4);
        }

        #pragma unroll
        for (int off = 16; off > 0; off >>= 1) {
            l  += __shfl_xor_sync(0xffffffffu, l,  off);
            s0 += __shfl_xor_sync(0xffffffffu, s0, off);
            s1 += __shfl_xor_sync(0xffffffffu, s1, off);
            s2 += __shfl_xor_sync(0xffffffffu, s2, off);
            s3 += __shfl_xor_sync(0xffffffffu, s3, off);
            s4 += __shfl_xor_sync(0xffffffffu, s4, off);
        }

        if (lane == 0) {
            const float gate = (l > 0.0f) ? 1.0f : 0.0f;
            const float inv  = (l > 0.0f) ? __fdividef(1.0f, l) : 0.0f;
            const float t0 = s0*inv, t1 = s1*inv, t2 = s2*inv, t3 = s3*inv, t4 = s4*inv;
            #pragma unroll
            for (int d = 0; d < HD; d++) {
                const int hd = h*HD + d;
                float c = sbv[hd];
                c = fmaf(t0, sWv[hd*INTR_D + 0], c);
                c = fmaf(t1, sWv[hd*INTR_D + 1], c);
                c = fmaf(t2, sWv[hd*INTR_D + 2], c);
                c = fmaf(t3, sWv[hd*INTR_D + 3], c);
                c = fmaf(t4, sWv[hd*INTR_D + 4], c);
                g_x[(size_t)row*IN_DIM + OWN_D + hd] = c * gate;
            }
        }
    }

    if (lane < OWN_D) g_x[(size_t)row*IN_DIM + lane] = __ldg(orow + lane);
}

// ---------------------------------------------------------------------------
// Kernel B: fused MLP (FFMA2) — R10 geometry; x1 phase packed via f32x2 with
// memory-sourced row pairs (sXT transposed: [dim][32 rows]).
// CTA = 32 rows x 256 cols, 128 threads (4 warps), grid 512, 4 CTAs/SM.
// ---------------------------------------------------------------------------
#define KCH    16
#define NCHUNK (HID/KCH)                     // 16
#define X1STR  68                            // floats: 64 dup + 4 pad
#define OFF_W2 0                             // [2][KCH][256] f32 = 32768 B
#define OFF_X1 32768                         // [2][KCH][X1STR] f32 = 8704 B
#define OFF_SX (32768 + 8704)                // sXT [22][32] f32 = 2816 B
#define SMEM_MLP (OFF_SX + 2816)             // 44288 B

__global__ void __launch_bounds__(128, 4) mlp_kernel(
    const float* __restrict__ W1, const float* __restrict__ b1,
    const float* __restrict__ W2, const float* __restrict__ b2,
    const float* __restrict__ Wf, const float* __restrict__ bf,
    const float* __restrict__ log_std, float* __restrict__ out)
{
    extern __shared__ __align__(16) char dsm[];
    float* sW2 = (float*)(dsm + OFF_W2);
    float* sX1 = (float*)(dsm + OFF_X1);
    float* sXT = (float*)(dsm + OFF_SX);     // [22][32] transposed
    const uint32_t w2b = s2u(sW2);

    const int tid  = threadIdx.x;
    const int ct   = tid & 31;               // lane
    const int rg   = tid >> 5;               // warp: rows r0..r0+7
    const int cl   = ct * 4;                 // low-half col base
    const int r0   = rg * 8;
    const int row0 = blockIdx.x * 32;

    // x1-compute mapping: col = kk + (tid&15), rows 4q..4q+3
    const int xc = tid & 15;
    const int q  = tid >> 4;
    const int rb = 4*q;

    // prefetch W2 chunk 0 (16KB, 128 threads x 8 x 16B)
    #pragma unroll
    for (int u = 0; u < 8; u++) {
        const int idx = u*128 + tid;
        cp_async16(w2b + idx*16, W2 + idx*4);
    }
    cp_commit();

    // stage x rows TRANSPOSED: sXT[i][r]
    for (int idx = tid; idx < 32*IN_DIM; idx += 128) {
        const int r = idx / IN_DIM, i = idx - r*IN_DIM;
        sXT[i*32 + r] = g_x[(size_t)row0*IN_DIM + idx];
    }
    __syncthreads();

    ull acc[8][4];                 // [row j][p]: p<2 -> cl+2p, p>=2 -> 128+cl+2(p-2)
    #pragma unroll
    for (int j = 0; j < 8; j++)
        #pragma unroll
        for (int p = 0; p < 4; p++) acc[j][p] = 0ULL;

    for (int ch = 0; ch < NCHUNK; ch++) {
        const int kk  = ch * KCH;
        const int buf = ch & 1;

        // ---- x1 for col kk+xc, rows rb..rb+3, packed f32x2 ----
        {
            const float bb = __ldg(b1 + kk + xc);
            ull ar01 = pack2(bb, bb), ar23 = pack2(bb, bb);
            const float* w1c = W1 + kk + xc;
            #pragma unroll
            for (int i = 0; i < IN_DIM; i++) {
                const float wv = __ldg(w1c + i*HID);
                const ull wd = pack2(wv, wv);
                const ull x01 = *(const ull*)&sXT[i*32 + rb];
                const ull x23 = *(const ull*)&sXT[i*32 + rb + 2];
                fma2(ar01, x01, wd);
                fma2(ar23, x23, wd);
            }
            float a0, a1, a2, a3;
            unpack2(ar01, a0, a1);
            unpack2(ar23, a2, a3);
            a0 = (a0 > 0.0f) ? a0 : 0.2f*a0;
            a1 = (a1 > 0.0f) ? a1 : 0.2f*a1;
            a2 = (a2 > 0.0f) ? a2 : 0.2f*a2;
            a3 = (a3 > 0.0f) ? a3 : 0.2f*a3;
            float* xd = sX1 + buf*(KCH*X1STR) + xc*X1STR + 8*q;
            *(float4*)(xd)     = make_float4(a0, a0, a1, a1);
            *(float4*)(xd + 4) = make_float4(a2, a2, a3, a3);
        }

        cp_wait0();            // W2 chunk ch landed
        __syncthreads();       // x1[buf] + W2[buf] visible (4-warp barrier)

        // prefetch next W2 chunk (overlaps FFMA2 loop)
        if (ch < NCHUNK-1) {
            const uint32_t dst = w2b + (buf ^ 1)*(KCH*256*4);
            const float* src = W2 + (size_t)(kk + KCH)*HID;
            #pragma unroll
            for (int u = 0; u < 8; u++) {
                const int idx = u*128 + tid;
                cp_async16(dst + idx*16, src + idx*4);
            }
            cp_commit();
        }

        // ---- FFMA2 inner loop: W loads lane-contiguous (4 wavefronts) ----
        const float* Wb = sW2 + buf*(KCH*256);
        const float* Xb = sX1 + buf*(KCH*X1STR) + 2*r0;
        #pragma unroll
        for (int k = 0; k < KCH; k++) {
            const ulonglong2* xp = (const ulonglong2*)(Xb + k*X1STR);
            const ulonglong2 xa = xp[0], xb_ = xp[1], xc_ = xp[2], xd_ = xp[3];
            const ulonglong2 wa = *(const ulonglong2*)(Wb + k*256 + cl);
            const ulonglong2 wb_ = *(const ulonglong2*)(Wb + k*256 + 128 + cl);

            fma2(acc[0][0], xa.x,  wa.x);  fma2(acc[0][1], xa.x,  wa.y);
            fma2(acc[0][2], xa.x,  wb_.x); fma2(acc[0][3], xa.x,  wb_.y);
            fma2(acc[1][0], xa.y,  wa.x);  fma2(acc[1][1], xa.y,  wa.y);
            fma2(acc[1][2], xa.y,  wb_.x); fma2(acc[1][3], xa.y,  wb_.y);
            fma2(acc[2][0], xb_.x, wa.x);  fma2(acc[2][1], xb_.x, wa.y);
            fma2(acc[2][2], xb_.x, wb_.x); fma2(acc[2][3], xb_.x, wb_.y);
            fma2(acc[3][0], xb_.y, wa.x);  fma2(acc[3][1], xb_.y, wa.y);
            fma2(acc[3][2], xb_.y, wb_.x); fma2(acc[3][3], xb_.y, wb_.y);
            fma2(acc[4][0], xc_.x, wa.x);  fma2(acc[4][1], xc_.x, wa.y);
            fma2(acc[4][2], xc_.x, wb_.x); fma2(acc[4][3], xc_.x, wb_.y);
            fma2(acc[5][0], xc_.y, wa.x);  fma2(acc[5][1], xc_.y, wa.y);
            fma2(acc[5][2], xc_.y, wb_.x); fma2(acc[5][3], xc_.y, wb_.y);
            fma2(acc[6][0], xd_.x, wa.x);  fma2(acc[6][1], xd_.x, wa.y);
            fma2(acc[6][2], xd_.x, wb_.x); fma2(acc[6][3], xd_.x, wb_.y);
            fma2(acc[7][0], xd_.y, wa.x);  fma2(acc[7][1], xd_.y, wa.y);
            fma2(acc[7][2], xd_.y, wb_.x); fma2(acc[7][3], xd_.y, wb_.y);
        }
    }

    // ---- epilogue: b2 + leaky + Wf projection ----
    float po0[8], po1[8];
    #pragma unroll
    for (int j = 0; j < 8; j++) { po0[j] = 0.0f; po1[j] = 0.0f; }

    #pragma unroll
    for (int p = 0; p < 4; p++) {
        const int c = (p < 2) ? (cl + 2*p) : (128 + cl + 2*(p - 2));
        const float b2a = __ldg(b2 + c),       b2b = __ldg(b2 + c + 1);
        const float wa0 = __ldg(Wf + c*2),     wa1 = __ldg(Wf + c*2 + 1);
        const float wb0 = __ldg(Wf + c*2 + 2), wb1 = __ldg(Wf + c*2 + 3);
        #pragma unroll
        for (int j = 0; j < 8; j++) {
            float vl, vh;
            unpack2(acc[j][p], vl, vh);
            vl += b2a; vl = (vl > 0.0f) ? vl : 0.2f*vl;
            vh += b2b; vh = (vh > 0.0f) ? vh : 0.2f*vh;
            po0[j] += vl*wa0 + vh*wb0;
            po1[j] += vl*wa1 + vh*wb1;
        }
    }

    #pragma unroll
    for (int off = 16; off > 0; off >>= 1) {
        #pragma unroll
        for (int j = 0; j < 8; j++) {
            po0[j] += __shfl_xor_sync(0xffffffffu, po0[j], off);
            po1[j] += __shfl_xor_sync(0xffffffffu, po1[j], off);
        }
    }

    if (ct == 0) {
        const float bf0 = __ldg(bf + 0), bf1 = __ldg(bf + 1);
        const float ls0 = __ldg(log_std + 0), ls1 = __ldg(log_std + 1);
        #pragma unroll
        for (int j = 0; j < 8; j++) {
            float4 o;
            o.x = po0[j] + bf0;
            o.y = po1[j] + bf1;
            o.z = ls0;
            o.w = ls1;
            *(float4*)&out[(size_t)(row0 + r0 + j)*4] = o;
        }
    }
}

// ---------------------------------------------------------------------------
extern "C" void kernel_launch(void* const* d_in, const int* in_sizes, int n_in,
                              void* d_out, int out_size)
{
    const float* obs         = (const float*)d_in[0];
    const float* Wq          = (const float*)d_in[1];
    const float* bq          = (const float*)d_in[2];
    const float* Wk          = (const float*)d_in[3];
    const float* bk          = (const float*)d_in[4];
    const float* Wv          = (const float*)d_in[5];
    const float* bv          = (const float*)d_in[6];
    const float* v_att       = (const float*)d_in[7];
    const float* temperature = (const float*)d_in[8];
    const float* W1          = (const float*)d_in[9];
    const float* b1          = (const float*)d_in[10];
    const float* W2          = (const float*)d_in[11];
    const float* b2          = (const float*)d_in[12];
    const float* Wf          = (const float*)d_in[13];
    const float* bf          = (const float*)d_in[14];
    const float* log_std     = (const float*)d_in[15];
    float* out = (float*)d_out;

    cudaFuncSetAttribute(mlp_kernel,
                         cudaFuncAttributeMaxDynamicSharedMemorySize,
                         SMEM_MLP);

    attn_kernel<<<NB/4, 128>>>(obs, Wq, bq, Wk, bk, Wv, bv, v_att, temperature);
    mlp_kernel<<<NB/32, 128, SMEM_MLP>>>(W1, b1, W2, b2, Wf, bf, log_std, out);
}